// round 1
// baseline (speedup 1.0000x reference)
#include <cuda_runtime.h>

// ---------------------------------------------------------------------------
// EMA Vector Quantizer (VQ-VAE codebook) for GB300 sm_103a
//
// inputs  [16, 64, 64, 64] f32   (B, C, H, W)   -> N = 65536 vectors, dim 64
// weight  [4096, 64] f32
// ema_cluster_size [4096] f32 (zeros), ema_w [4096, 64] f32 (== weight)
//
// Output (concatenated f32, in reference tuple order):
//   quantized_ste [4194304], loss [1], encoding_indices [65536],
//   new_weight [262144], new_cluster_size [4096], new_ema_w [262144]
// ---------------------------------------------------------------------------

#define NUM_E   4096
#define CDIM    64
#define NVEC    65536
#define SPATIAL 4096          // H*W
#define BM      128           // x rows per block
#define BN      256           // codewords per K-tile
#define TM      8             // rows per thread
#define TN      16            // cols per thread
#define THREADS 256
#define KTILES  (NUM_E / BN)  // 16

#define OFF_Q    0
#define OFF_LOSS 4194304
#define OFF_IDX  4194305
#define OFF_W    (OFF_IDX + NVEC)          // 4259841
#define OFF_CS   (OFF_W + NUM_E * CDIM)    // 4521985
#define OFF_EW   (OFF_CS + NUM_E)          // 4526081

#define SMEM_BYTES ((CDIM*BM + CDIM*BN + BN) * 4)   // 99328

// Scratch (device globals; no allocations allowed)
__device__ float g_counts[NUM_E];
__device__ float g_dw[NUM_E * CDIM];
__device__ float g_wn[NUM_E];
__device__ float g_loss;
__device__ float g_n;

// ---- packed fp32x2 helpers (sm_100+ PTX) ----------------------------------
__device__ __forceinline__ void ffma2(unsigned long long& d,
                                      unsigned long long a,
                                      unsigned long long b) {
    asm("fma.rn.f32x2 %0, %1, %2, %0;" : "+l"(d) : "l"(a), "l"(b));
}
__device__ __forceinline__ unsigned long long dup_f32(float x) {
    unsigned long long r;
    unsigned int u = __float_as_uint(x);
    asm("mov.b64 %0, {%1, %1};" : "=l"(r) : "r"(u));
    return r;
}
__device__ __forceinline__ void unpack2(unsigned long long v, float& lo, float& hi) {
    unsigned int a, b;
    asm("mov.b64 {%0, %1}, %2;" : "=r"(a), "=r"(b) : "l"(v));
    lo = __uint_as_float(a);
    hi = __uint_as_float(b);
}

// ---------------------------------------------------------------------------
// prep: zero scratch + wnorm[k] = sum_c w[k][c]^2
// ---------------------------------------------------------------------------
__global__ void prep_kernel(const float* __restrict__ weight) {
    int i = blockIdx.x * blockDim.x + threadIdx.x;   // 262144 threads
    if (i < NUM_E * CDIM) g_dw[i] = 0.0f;
    if (i < NUM_E) {
        const float4* wrow = reinterpret_cast<const float4*>(weight + (size_t)i * CDIM);
        float s = 0.0f;
#pragma unroll
        for (int j = 0; j < CDIM / 4; ++j) {
            float4 v = wrow[j];
            s += v.x * v.x + v.y * v.y + v.z * v.z + v.w * v.w;
        }
        g_wn[i] = s;
        g_counts[i] = 0.0f;
    }
    if (i == 0) { g_loss = 0.0f; g_n = 0.0f; }
}

// ---------------------------------------------------------------------------
// main: fused argmin-GEMM + gather + loss partial + dw/count scatter
// score(k) = wnorm[k] - 2 * <x, w_k>   (xnorm dropped: argmin-invariant)
// ---------------------------------------------------------------------------
__global__ void __launch_bounds__(THREADS, 1)
argmin_kernel(const float* __restrict__ inputs,
              const float* __restrict__ weight,
              float* __restrict__ out)
{
    extern __shared__ char smem[];
    float* Xs  = (float*)smem;                               // [64][128]
    float* Ws  = (float*)(smem + CDIM * BM * 4);             // [64][256] swizzled
    float* wnS = (float*)(smem + (CDIM * BM + CDIM * BN) * 4); // [256]

    const int tid = threadIdx.x;
    const int tx  = tid & 15;    // col group (16)
    const int ty  = tid >> 4;    // row group (16)

    const int n0  = blockIdx.x * BM;
    const int b   = n0 >> 12;           // / SPATIAL
    const int hw0 = n0 & (SPATIAL - 1);
    const float* inb = inputs + ((size_t)b * CDIM) * SPATIAL + hw0;

    // ---- load X tile: Xs[c][r] -----------------------------------------
#pragma unroll
    for (int it = 0; it < (CDIM * BM) / (THREADS * 4); ++it) {   // 8 iters
        int fl = (it * THREADS + tid) * 4;
        int c  = fl >> 7;
        int r  = fl & (BM - 1);
        float4 v = *reinterpret_cast<const float4*>(inb + (size_t)c * SPATIAL + r);
        *reinterpret_cast<float4*>(Xs + fl) = v;     // fl == c*128 + r
    }

    float best[TM];
    int   bestk[TM];
#pragma unroll
    for (int r = 0; r < TM; ++r) { best[r] = 3.4e38f; bestk[r] = 0; }

    for (int t = 0; t < KTILES; ++t) {
        const int k0 = t * BN;
        __syncthreads();   // Ws free to rewrite; Xs visible (first iter)

        // ---- load W tile, transpose to [c][k] with XOR swizzle ----------
        const float* wt = weight + (size_t)k0 * CDIM;
#pragma unroll
        for (int it = 0; it < (CDIM * BN) / (THREADS * 4); ++it) {   // 16 iters
            int fl = (it * THREADS + tid) * 4;   // = k*64 + c
            int k  = fl >> 6;
            int c  = fl & (CDIM - 1);
            float4 v = *reinterpret_cast<const float4*>(wt + fl);
            int k4 = k >> 2, ki = k & 3;
            float vv[4] = {v.x, v.y, v.z, v.w};
#pragma unroll
            for (int q = 0; q < 4; ++q) {
                int cc = c + q;
                int unit = cc * 64 + (k4 ^ ((cc >> 2) & 7));
                Ws[unit * 4 + ki] = vv[q];
            }
        }
        if (tid < BN / 4) {
            *reinterpret_cast<float4*>(wnS + tid * 4) =
                *reinterpret_cast<const float4*>(g_wn + k0 + tid * 4);
        }
        __syncthreads();

        // ---- register-tile GEMM, packed f32x2 along k -------------------
        unsigned long long acc[TM][8];
#pragma unroll
        for (int r = 0; r < TM; ++r)
#pragma unroll
            for (int jj = 0; jj < 8; ++jj) acc[r][jj] = 0ULL;

#pragma unroll 4
        for (int c = 0; c < CDIM; ++c) {
            float4 xa = *reinterpret_cast<const float4*>(Xs + c * BM + ty * TM);
            float4 xb = *reinterpret_cast<const float4*>(Xs + c * BM + ty * TM + 4);
            unsigned long long xx[TM];
            xx[0] = dup_f32(xa.x); xx[1] = dup_f32(xa.y);
            xx[2] = dup_f32(xa.z); xx[3] = dup_f32(xa.w);
            xx[4] = dup_f32(xb.x); xx[5] = dup_f32(xb.y);
            xx[6] = dup_f32(xb.z); xx[7] = dup_f32(xb.w);
            int sw = (c >> 2) & 7;
#pragma unroll
            for (int j = 0; j < 4; ++j) {
                int k4   = tx + 16 * j;
                int unit = c * 64 + (k4 ^ sw);
                float4 wv = *reinterpret_cast<const float4*>(Ws + unit * 4);
                unsigned long long w0 = reinterpret_cast<unsigned long long*>(&wv)[0];
                unsigned long long w1 = reinterpret_cast<unsigned long long*>(&wv)[1];
#pragma unroll
                for (int r = 0; r < TM; ++r) {
                    ffma2(acc[r][2 * j],     xx[r], w0);
                    ffma2(acc[r][2 * j + 1], xx[r], w1);
                }
            }
        }

        // ---- argmin epilogue for this tile (k ascending -> first-min) ----
#pragma unroll
        for (int j = 0; j < 4; ++j) {
            int klbase = tx * 4 + j * 64;
#pragma unroll
            for (int p = 0; p < 2; ++p) {
                int kl  = klbase + 2 * p;
                float wn0 = wnS[kl];
                float wn1 = wnS[kl + 1];
                int kg = k0 + kl;
#pragma unroll
                for (int r = 0; r < TM; ++r) {
                    float d0, d1;
                    unpack2(acc[r][2 * j + p], d0, d1);
                    float s0 = fmaf(-2.0f, d0, wn0);
                    float s1 = fmaf(-2.0f, d1, wn1);
                    if (s0 < best[r]) { best[r] = s0; bestk[r] = kg; }
                    if (s1 < best[r]) { best[r] = s1; bestk[r] = kg + 1; }
                }
            }
        }
    }

    // ---- cross-thread argmin reduction (alias Ws region) ----------------
    __syncthreads();
    float* red_s = Ws;                        // [16][BM]
    int*   red_k = (int*)(Ws + 16 * BM);      // [16][BM]
    int*   idx_s = (int*)(Ws + 32 * BM);      // [BM]
#pragma unroll
    for (int r = 0; r < TM; ++r) {
        int row = ty * TM + r;
        red_s[tx * BM + row] = best[r];
        red_k[tx * BM + row] = bestk[r];
    }
    __syncthreads();
    if (tid < BM) {
        float bs = red_s[tid];
        int   bk = red_k[tid];
#pragma unroll
        for (int u = 1; u < 16; ++u) {
            float s = red_s[u * BM + tid];
            int   k = red_k[u * BM + tid];
            if (s < bs || (s == bs && k < bk)) { bs = s; bk = k; }
        }
        idx_s[tid] = bk;
        out[OFF_IDX + n0 + tid] = (float)bk;
        atomicAdd(&g_counts[bk], 1.0f);
    }
    __syncthreads();

    // ---- gather quantized, loss partial, dw scatter ----------------------
    float lsum = 0.0f;
    float* outq = out + OFF_Q + ((size_t)b * CDIM) * SPATIAL + hw0;
    for (int t2 = tid; t2 < CDIM * BM; t2 += THREADS) {
        int c = t2 >> 7;
        int r = t2 & (BM - 1);
        int kidx = idx_s[r];
        float q = weight[(size_t)kidx * CDIM + c];
        float x = Xs[t2];
        outq[(size_t)c * SPATIAL + r] = q;
        float d = x - q;
        lsum += d * d;
        atomicAdd(&g_dw[kidx * CDIM + c], x);
    }
#pragma unroll
    for (int o = 16; o > 0; o >>= 1)
        lsum += __shfl_xor_sync(0xffffffffu, lsum, o);
    if ((tid & 31) == 0) red_s[tid >> 5] = lsum;
    __syncthreads();
    if (tid == 0) {
        float s = 0.0f;
#pragma unroll
        for (int w = 0; w < THREADS / 32; ++w) s += red_s[w];
        atomicAdd(&g_loss, s);
    }
}

// ---------------------------------------------------------------------------
// finalize 1: new_cluster_size + global sum n
// ---------------------------------------------------------------------------
__global__ void finalize1_kernel(const float* __restrict__ ema_cs,
                                 float* __restrict__ out) {
    int k = blockIdx.x * blockDim.x + threadIdx.x;   // 4096 threads
    float ncs = 0.99f * ema_cs[k] + 0.01f * g_counts[k];
    out[OFF_CS + k] = ncs;
    float s = ncs;
#pragma unroll
    for (int o = 16; o > 0; o >>= 1)
        s += __shfl_xor_sync(0xffffffffu, s, o);
    __shared__ float sh[8];
    if ((threadIdx.x & 31) == 0) sh[threadIdx.x >> 5] = s;
    __syncthreads();
    if (threadIdx.x == 0) {
        float t = 0.0f;
#pragma unroll
        for (int w = 0; w < 8; ++w) t += sh[w];
        atomicAdd(&g_n, t);
    }
}

// ---------------------------------------------------------------------------
// finalize 2: new_ema_w, new_weight, loss scalar
// ---------------------------------------------------------------------------
__global__ void finalize2_kernel(const float* __restrict__ ema_w,
                                 float* __restrict__ out) {
    int i = blockIdx.x * blockDim.x + threadIdx.x;   // 262144 threads
    int k = i >> 6;
    float n   = g_n;
    float ncs = out[OFF_CS + k];
    float cs  = (ncs + 1e-5f) / (n + (float)NUM_E * 1e-5f) * n;
    float ne  = 0.99f * ema_w[i] + 0.01f * g_dw[i];
    out[OFF_EW + i] = ne;
    out[OFF_W + i]  = ne / cs;
    if (i == 0) out[OFF_LOSS] = 0.25f * g_loss / 4194304.0f;
}

// ---------------------------------------------------------------------------
extern "C" void kernel_launch(void* const* d_in, const int* in_sizes, int n_in,
                              void* d_out, int out_size) {
    const float* inputs = (const float*)d_in[0];
    const float* weight = (const float*)d_in[1];
    const float* ema_cs = (const float*)d_in[2];
    const float* ema_w  = (const float*)d_in[3];
    float* out = (float*)d_out;

    cudaFuncSetAttribute(argmin_kernel,
                         cudaFuncAttributeMaxDynamicSharedMemorySize, SMEM_BYTES);

    prep_kernel<<<(NUM_E * CDIM) / 256, 256>>>(weight);
    argmin_kernel<<<NVEC / BM, THREADS, SMEM_BYTES>>>(inputs, weight, out);
    finalize1_kernel<<<NUM_E / 256, 256>>>(ema_cs, out);
    finalize2_kernel<<<(NUM_E * CDIM) / 256, 256>>>(ema_w, out);
}

// round 3
// speedup vs baseline: 1.4211x; 1.4211x over previous
#include <cuda_runtime.h>
#include <cuda_fp16.h>

// ---------------------------------------------------------------------------
// EMA Vector Quantizer, round 3: mma.sync (HMMA) fp16 argmin-GEMM
//   + exact fp32 margin-based fixup. No sm_103a-only instructions.
// ---------------------------------------------------------------------------

#define NUM_E   4096
#define CDIM    64
#define NVEC    65536
#define BM      128
#define BN      128          // codes per tile iteration
#define NTILES  (NUM_E / BN) // 32
#define THREADS 256
#define MARGIN  0.10f

#define OFF_Q    0
#define OFF_LOSS 4194304
#define OFF_IDX  4194305
#define OFF_W    (OFF_IDX + NVEC)
#define OFF_CS   (OFF_W + NUM_E * CDIM)
#define OFF_EW   (OFF_CS + NUM_E)

// smem layout
#define SM_X       0                       // 128 rows x 128B (f16, swizzled)
#define SM_WBUF(b) (16384 + (b) * 17408)   // 64 dim-rows x 256B (f16, swizzled)
#define SM_WN(b)   (SM_WBUF(b) + 16384)    // 128 floats
#define SMEM_TOTAL (16384 + 2 * 17408)     // 51200

// device scratch
__device__ __half g_w16t[CDIM * NUM_E];   // transposed codebook [dim][code]
__device__ float  g_wn[NUM_E];
__device__ float  g_counts[NUM_E];
__device__ float  g_dw[NUM_E * CDIM];
__device__ int    g_bestk[NVEC];
__device__ int    g_amb[NVEC];
__device__ int    g_namb;
__device__ float  g_loss;
__device__ float  g_n;

// ---- PTX helpers -----------------------------------------------------------
__device__ __forceinline__ unsigned smem_u32(const void* p) {
    return (unsigned)__cvta_generic_to_shared(p);
}
__device__ __forceinline__ void ldsm4(unsigned* r, unsigned addr) {
    asm volatile("ldmatrix.sync.aligned.m8n8.x4.shared.b16 {%0,%1,%2,%3}, [%4];"
                 : "=r"(r[0]), "=r"(r[1]), "=r"(r[2]), "=r"(r[3]) : "r"(addr));
}
__device__ __forceinline__ void ldsm4t(unsigned* r, unsigned addr) {
    asm volatile("ldmatrix.sync.aligned.m8n8.x4.trans.shared.b16 {%0,%1,%2,%3}, [%4];"
                 : "=r"(r[0]), "=r"(r[1]), "=r"(r[2]), "=r"(r[3]) : "r"(addr));
}
__device__ __forceinline__ void mma16816(float* c, const unsigned* a,
                                         unsigned b0, unsigned b1) {
    asm volatile("mma.sync.aligned.m16n8k16.row.col.f32.f16.f16.f32 "
                 "{%0,%1,%2,%3}, {%4,%5,%6,%7}, {%8,%9}, {%0,%1,%2,%3};"
                 : "+f"(c[0]), "+f"(c[1]), "+f"(c[2]), "+f"(c[3])
                 : "r"(a[0]), "r"(a[1]), "r"(a[2]), "r"(a[3]), "r"(b0), "r"(b1));
}
__device__ __forceinline__ void cpa16(unsigned dst, const void* src) {
    asm volatile("cp.async.cg.shared.global [%0], [%1], 16;"
                 :: "r"(dst), "l"(src) : "memory");
}

// ---------------------------------------------------------------------------
// prep: transpose codebook to fp16 [dim][code], wn, zero scratch
// ---------------------------------------------------------------------------
__global__ void prep_kernel(const float* __restrict__ weight) {
    int i = blockIdx.x * blockDim.x + threadIdx.x;   // 262144
    float w = weight[i];
    int code = i >> 6, c = i & 63;
    g_w16t[(size_t)c * NUM_E + code] = __float2half_rn(w);
    g_dw[i] = 0.0f;
    if (i < NUM_E) {
        const float4* wrow = reinterpret_cast<const float4*>(weight + (size_t)i * CDIM);
        float s = 0.0f;
#pragma unroll
        for (int j = 0; j < CDIM / 4; ++j) {
            float4 v = wrow[j];
            s += v.x * v.x + v.y * v.y + v.z * v.z + v.w * v.w;
        }
        g_wn[i] = s;
        g_counts[i] = 0.0f;
    }
    if (i == 0) { g_loss = 0.0f; g_n = 0.0f; g_namb = 0; }
}

// ---------------------------------------------------------------------------
// argmin kernel: HMMA GEMM + streaming best/best2/argmin
// ---------------------------------------------------------------------------
__global__ void __launch_bounds__(THREADS, 1)
argmin_kernel(const float* __restrict__ inputs)
{
    extern __shared__ char smem[];
    const unsigned sb = smem_u32(smem);
    const int tid  = threadIdx.x;
    const int lane = tid & 31;
    const int wid  = tid >> 5;
    const int wm   = wid >> 1;        // 0..3 (m32 slice)
    const int wnh  = wid & 1;         // 0..1 (n64 half)

    const int n0  = blockIdx.x * BM;
    const int bB  = n0 >> 12;
    const int hw0 = n0 & 4095;

    // ---- load X, convert to fp16 into Xs[row][dim] (swizzled) ----------
    const float* xb = inputs + (size_t)bB * (CDIM * 4096) + hw0;
#pragma unroll
    for (int it = 0; it < 4; ++it) {
        int idx = it * 256 + tid;        // 0..1023
        int c = (idx & 31) * 2;          // 0..62
        int r = (idx >> 5) * 4;          // 0..124
        float4 f0 = *reinterpret_cast<const float4*>(xb + (size_t)c * 4096 + r);
        float4 f1 = *reinterpret_cast<const float4*>(xb + (size_t)(c + 1) * 4096 + r);
        const float* p0 = &f0.x; const float* p1 = &f1.x;
#pragma unroll
        for (int q = 0; q < 4; ++q) {
            int row = r + q;
            __half2 h = __floats2half2_rn(p0[q], p1[q]);
            unsigned off = row * 128 + (((c >> 3) ^ (row & 7)) * 16) + (c & 7) * 2;
            *reinterpret_cast<__half2*>(smem + off) = h;
        }
    }
    __syncthreads();

    // ---- A fragments: whole m32 x k64 slice in registers ---------------
    unsigned afr[2][4][4];
#pragma unroll
    for (int i = 0; i < 2; ++i)
#pragma unroll
        for (int k = 0; k < 4; ++k) {
            int row = wm * 32 + i * 16 + (lane & 15);
            int ch  = (k * 2 + (lane >> 4)) ^ (row & 7);
            ldsm4(afr[i][k], sb + row * 128 + ch * 16);
        }

    // B ldmatrix per-lane address offsets (relative to buffer base)
    unsigned boff[4][4];
#pragma unroll
    for (int k = 0; k < 4; ++k)
#pragma unroll
        for (int jj = 0; jj < 4; ++jj) {
            int row = k * 16 + (lane & 15);
            int ch  = (wnh * 8 + jj * 2 + (lane >> 4)) ^ (row & 7);
            boff[k][jj] = row * 256 + ch * 16;
        }

    float best[4], best2[4]; int bk[4];
#pragma unroll
    for (int s = 0; s < 4; ++s) { best[s] = 3.4e38f; best2[s] = 3.4e38f; bk[s] = 0; }

    const int wnidx = (wnh * 64 + 2 * (lane & 3)) * 4;   // byte off into wn stage

    // ---- prologue: tile 0 ----------------------------------------------
    {
        int kt = 0;
#pragma unroll
        for (int j = 0; j < 4; ++j) {
            int idx = j * 256 + tid;
            int row = idx >> 4, c = idx & 15;
            cpa16(sb + SM_WBUF(0) + row * 256 + ((c ^ (row & 7)) * 16),
                  g_w16t + (size_t)row * NUM_E + kt + c * 8);
        }
        if (tid < 32) cpa16(sb + SM_WN(0) + tid * 16, g_wn + kt + tid * 4);
        asm volatile("cp.async.commit_group;" ::: "memory");
    }

    for (int t = 0; t < NTILES; ++t) {
        if (t + 1 < NTILES) {
            int kt = (t + 1) * BN, b = (t + 1) & 1;
#pragma unroll
            for (int j = 0; j < 4; ++j) {
                int idx = j * 256 + tid;
                int row = idx >> 4, c = idx & 15;
                cpa16(sb + SM_WBUF(b) + row * 256 + ((c ^ (row & 7)) * 16),
                      g_w16t + (size_t)row * NUM_E + kt + c * 8);
            }
            if (tid < 32) cpa16(sb + SM_WN(b) + tid * 16, g_wn + kt + tid * 4);
            asm volatile("cp.async.commit_group;" ::: "memory");
            asm volatile("cp.async.wait_group 1;" ::: "memory");
        } else {
            asm volatile("cp.async.wait_group 0;" ::: "memory");
        }
        __syncthreads();

        const unsigned wbase = sb + SM_WBUF(t & 1);
        float acc[2][8][4];
#pragma unroll
        for (int i = 0; i < 2; ++i)
#pragma unroll
            for (int j = 0; j < 8; ++j)
#pragma unroll
                for (int e = 0; e < 4; ++e) acc[i][j][e] = 0.0f;

#pragma unroll
        for (int k = 0; k < 4; ++k) {
            unsigned bfr[4][4];
#pragma unroll
            for (int jj = 0; jj < 4; ++jj) ldsm4t(bfr[jj], wbase + boff[k][jj]);
#pragma unroll
            for (int i = 0; i < 2; ++i)
#pragma unroll
                for (int j = 0; j < 8; ++j)
                    mma16816(acc[i][j], afr[i][k], bfr[j >> 1][(j & 1) * 2],
                             bfr[j >> 1][(j & 1) * 2 + 1]);
        }

        // ---- epilogue: scores + streaming 2-min ------------------------
        const int ktb = t * BN + wnh * 64 + 2 * (lane & 3);
        const char* wnst = smem + SM_WN(t & 1);
#pragma unroll
        for (int j = 0; j < 8; ++j) {
            float2 wn2 = *reinterpret_cast<const float2*>(wnst + wnidx + j * 32);
            int cb = ktb + j * 8;
#pragma unroll
            for (int i = 0; i < 2; ++i) {
#pragma unroll
                for (int hlf = 0; hlf < 2; ++hlf) {
                    int sl = i * 2 + hlf;
                    float s0 = fmaf(-2.0f, acc[i][j][hlf * 2 + 0], wn2.x);
                    float s1 = fmaf(-2.0f, acc[i][j][hlf * 2 + 1], wn2.y);
                    bool lt0 = s0 < best[sl];
                    float old0 = best[sl];
                    best[sl]  = lt0 ? s0 : old0;
                    best2[sl] = fminf(best2[sl], lt0 ? old0 : s0);
                    bk[sl]    = lt0 ? cb : bk[sl];
                    bool lt1 = s1 < best[sl];
                    float old1 = best[sl];
                    best[sl]  = lt1 ? s1 : old1;
                    best2[sl] = fminf(best2[sl], lt1 ? old1 : s1);
                    bk[sl]    = lt1 ? (cb + 1) : bk[sl];
                }
            }
        }
        __syncthreads();
    }

    // ---- cross-lane (quad) reduction ------------------------------------
#pragma unroll
    for (int off = 1; off <= 2; off <<= 1) {
#pragma unroll
        for (int s = 0; s < 4; ++s) {
            float ob  = __shfl_xor_sync(0xffffffffu, best[s], off);
            float ob2 = __shfl_xor_sync(0xffffffffu, best2[s], off);
            int   ok  = __shfl_xor_sync(0xffffffffu, bk[s], off);
            float nb2 = fminf(fminf(best2[s], ob2), fmaxf(best[s], ob));
            bool take = (ob < best[s]) || (ob == best[s] && ok < bk[s]);
            best[s] = take ? ob : best[s];
            bk[s]   = take ? ok : bk[s];
            best2[s] = nb2;
        }
    }

    // ---- stage per (row, n-half) results, merge halves -------------------
    float* mB  = reinterpret_cast<float*>(smem);         // [2][128]
    float* mB2 = mB + 256;
    int*   mK  = reinterpret_cast<int*>(mB2 + 256);
    __syncthreads();
    if ((lane & 3) == 0) {
#pragma unroll
        for (int s = 0; s < 4; ++s) {
            int row = wm * 32 + (s >> 1) * 16 + (lane >> 2) + (s & 1) * 8;
            mB [wnh * 128 + row] = best[s];
            mB2[wnh * 128 + row] = best2[s];
            mK [wnh * 128 + row] = bk[s];
        }
    }
    __syncthreads();
    if (tid < 128) {
        float b0 = mB[tid],        b1 = mB[128 + tid];
        float c0 = mB2[tid],       c1 = mB2[128 + tid];
        int   k0 = mK[tid],        k1 = mK[128 + tid];
        float nb2 = fminf(fminf(c0, c1), fmaxf(b0, b1));
        float nb; int nk;
        if (b1 < b0 || (b1 == b0 && k1 < k0)) { nb = b1; nk = k1; }
        else                                   { nb = b0; nk = k0; }
        g_bestk[n0 + tid] = nk;
        bool amb = (nb2 - nb) < MARGIN;
        unsigned m = __ballot_sync(0xffffffffu, amb);
        int basep = 0;
        if (lane == 0 && m) basep = atomicAdd(&g_namb, __popc(m));
        basep = __shfl_sync(0xffffffffu, basep, 0);
        if (amb) g_amb[basep + __popc(m & ((1u << lane) - 1u))] = n0 + tid;
    }
}

// ---------------------------------------------------------------------------
// fixup: exact fp32 rescan for ambiguous vectors
// ---------------------------------------------------------------------------
__global__ void fixup_kernel(const float* __restrict__ inputs,
                             const float* __restrict__ weight)
{
    __shared__ float xs[CDIM];
    __shared__ float rs[8];
    __shared__ int   rk[8];
    const int tid = threadIdx.x;   // 256
    const int namb = g_namb;

    for (int li = blockIdx.x; li < namb; li += gridDim.x) {
        int v  = g_amb[li];
        int bB = v >> 12, hw = v & 4095;
        if (tid < CDIM)
            xs[tid] = inputs[(size_t)bB * (CDIM * 4096) + (size_t)tid * 4096 + hw];
        __syncthreads();

        float best = 3.4e38f; int bestk = 0;
        for (int k = tid; k < NUM_E; k += 256) {
            const float4* wr = reinterpret_cast<const float4*>(weight + (size_t)k * CDIM);
            float dot = 0.0f;
#pragma unroll
            for (int j = 0; j < 16; ++j) {
                float4 w4 = wr[j];
                dot = fmaf(xs[4 * j + 0], w4.x, dot);
                dot = fmaf(xs[4 * j + 1], w4.y, dot);
                dot = fmaf(xs[4 * j + 2], w4.z, dot);
                dot = fmaf(xs[4 * j + 3], w4.w, dot);
            }
            float s = fmaf(-2.0f, dot, g_wn[k]);
            if (s < best) { best = s; bestk = k; }
        }
#pragma unroll
        for (int o = 16; o > 0; o >>= 1) {
            float ob = __shfl_xor_sync(0xffffffffu, best, o);
            int   ok = __shfl_xor_sync(0xffffffffu, bestk, o);
            if (ob < best || (ob == best && ok < bestk)) { best = ob; bestk = ok; }
        }
        if ((tid & 31) == 0) { rs[tid >> 5] = best; rk[tid >> 5] = bestk; }
        __syncthreads();
        if (tid == 0) {
            float fb = rs[0]; int fk = rk[0];
#pragma unroll
            for (int w = 1; w < 8; ++w)
                if (rs[w] < fb || (rs[w] == fb && rk[w] < fk)) { fb = rs[w]; fk = rk[w]; }
            g_bestk[v] = fk;
        }
        __syncthreads();
    }
}

// ---------------------------------------------------------------------------
// scatter: idx out, counts, quantized gather, loss, dw scatter
// ---------------------------------------------------------------------------
__global__ void scatter_kernel(const float* __restrict__ inputs,
                               const float* __restrict__ weight,
                               float* __restrict__ out)
{
    __shared__ int   idx_s[BM];
    __shared__ float red[8];
    const int tid = threadIdx.x;   // 256
    const int n0  = blockIdx.x * BM;
    const int bB  = n0 >> 12;
    const int hw0 = n0 & 4095;

    if (tid < BM) {
        int k = g_bestk[n0 + tid];
        idx_s[tid] = k;
        out[OFF_IDX + n0 + tid] = (float)k;
        atomicAdd(&g_counts[k], 1.0f);
    }
    __syncthreads();

    const float* xb = inputs + (size_t)bB * (CDIM * 4096) + hw0;
    float* outq     = out + OFF_Q + (size_t)bB * (CDIM * 4096) + hw0;
    float lsum = 0.0f;
    for (int t2 = tid; t2 < CDIM * BM; t2 += 256) {
        int c = t2 >> 7, r = t2 & 127;
        int k = idx_s[r];
        float x = xb[(size_t)c * 4096 + r];
        float q = weight[(size_t)k * CDIM + c];
        outq[(size_t)c * 4096 + r] = q;
        float d = x - q;
        lsum += d * d;
        atomicAdd(&g_dw[k * CDIM + c], x);
    }
#pragma unroll
    for (int o = 16; o > 0; o >>= 1)
        lsum += __shfl_xor_sync(0xffffffffu, lsum, o);
    if ((tid & 31) == 0) red[tid >> 5] = lsum;
    __syncthreads();
    if (tid == 0) {
        float s = 0.0f;
#pragma unroll
        for (int w = 0; w < 8; ++w) s += red[w];
        atomicAdd(&g_loss, s);
    }
}

// ---------------------------------------------------------------------------
__global__ void finalize1_kernel(const float* __restrict__ ema_cs,
                                 float* __restrict__ out) {
    int k = blockIdx.x * blockDim.x + threadIdx.x;
    float ncs = 0.99f * ema_cs[k] + 0.01f * g_counts[k];
    out[OFF_CS + k] = ncs;
    float s = ncs;
#pragma unroll
    for (int o = 16; o > 0; o >>= 1)
        s += __shfl_xor_sync(0xffffffffu, s, o);
    __shared__ float sh[8];
    if ((threadIdx.x & 31) == 0) sh[threadIdx.x >> 5] = s;
    __syncthreads();
    if (threadIdx.x == 0) {
        float t = 0.0f;
#pragma unroll
        for (int w = 0; w < 8; ++w) t += sh[w];
        atomicAdd(&g_n, t);
    }
}

__global__ void finalize2_kernel(const float* __restrict__ ema_w,
                                 float* __restrict__ out) {
    int i = blockIdx.x * blockDim.x + threadIdx.x;
    int k = i >> 6;
    float n   = g_n;
    float ncs = out[OFF_CS + k];
    float cs  = (ncs + 1e-5f) / (n + (float)NUM_E * 1e-5f) * n;
    float ne  = 0.99f * ema_w[i] + 0.01f * g_dw[i];
    out[OFF_EW + i] = ne;
    out[OFF_W + i]  = ne / cs;
    if (i == 0) out[OFF_LOSS] = 0.25f * g_loss / 4194304.0f;
}

// ---------------------------------------------------------------------------
extern "C" void kernel_launch(void* const* d_in, const int* in_sizes, int n_in,
                              void* d_out, int out_size) {
    const float* inputs = (const float*)d_in[0];
    const float* weight = (const float*)d_in[1];
    const float* ema_cs = (const float*)d_in[2];
    const float* ema_w  = (const float*)d_in[3];
    float* out = (float*)d_out;

    cudaFuncSetAttribute(argmin_kernel,
                         cudaFuncAttributeMaxDynamicSharedMemorySize, SMEM_TOTAL);

    prep_kernel<<<(NUM_E * CDIM) / 256, 256>>>(weight);
    argmin_kernel<<<NVEC / BM, THREADS, SMEM_TOTAL>>>(inputs);
    fixup_kernel<<<512, 256>>>(inputs, weight);
    scatter_kernel<<<NVEC / BM, 256>>>(inputs, weight, out);
    finalize1_kernel<<<NUM_E / 256, 256>>>(ema_cs, out);
    finalize2_kernel<<<(NUM_E * CDIM) / 256, 256>>>(ema_w, out);
}

// round 4
// speedup vs baseline: 2.3765x; 1.6723x over previous
#include <cuda_runtime.h>
#include <cuda_fp16.h>

// ---------------------------------------------------------------------------
// EMA Vector Quantizer, round 4: fp16-split (hi/lo) HMMA argmin-GEMM giving
// ~fp32-accurate scores (3 MMA passes: hh + lh + hl), margin fixup ~empty.
// ---------------------------------------------------------------------------

#define NUM_E   4096
#define CDIM    64
#define NVEC    65536
#define BM      128
#define BN      128
#define NTILES  (NUM_E / BN)
#define THREADS 256
#define MARGIN  1.0e-3f

#define OFF_Q    0
#define OFF_LOSS 4194304
#define OFF_IDX  4194305
#define OFF_W    (OFF_IDX + NVEC)
#define OFF_CS   (OFF_W + NUM_E * CDIM)
#define OFF_EW   (OFF_CS + NUM_E)

// smem layout
#define SM_XH      0                        // 128 x 128B fp16 hi (swizzled)
#define SM_XL      16384                    // 128 x 128B fp16 lo
#define SM_WST     32768
#define SM_WBUF(b) (SM_WST + (b) * 33280)   // hi 16KB | lo 16KB | wn 512B
#define SM_WLO(b)  (SM_WBUF(b) + 16384)
#define SM_WN(b)   (SM_WBUF(b) + 32768)
#define SMEM_TOTAL (SM_WST + 2 * 33280)     // 99328

// device scratch
__device__ __half g_wth[CDIM * NUM_E];    // [dim][code] hi
__device__ __half g_wtl[CDIM * NUM_E];    // [dim][code] lo
__device__ float  g_wn[NUM_E];
__device__ float  g_counts[NUM_E];
__device__ float  g_dw[NUM_E * CDIM];
__device__ int    g_bestk[NVEC];
__device__ int    g_amb[NVEC];
__device__ int    g_namb;
__device__ float  g_loss;
__device__ float  g_n;

// ---- PTX helpers -----------------------------------------------------------
__device__ __forceinline__ unsigned smem_u32(const void* p) {
    return (unsigned)__cvta_generic_to_shared(p);
}
__device__ __forceinline__ void ldsm4(unsigned* r, unsigned addr) {
    asm volatile("ldmatrix.sync.aligned.m8n8.x4.shared.b16 {%0,%1,%2,%3}, [%4];"
                 : "=r"(r[0]), "=r"(r[1]), "=r"(r[2]), "=r"(r[3]) : "r"(addr));
}
__device__ __forceinline__ void ldsm4t(unsigned* r, unsigned addr) {
    asm volatile("ldmatrix.sync.aligned.m8n8.x4.trans.shared.b16 {%0,%1,%2,%3}, [%4];"
                 : "=r"(r[0]), "=r"(r[1]), "=r"(r[2]), "=r"(r[3]) : "r"(addr));
}
__device__ __forceinline__ void mma16816(float* c, const unsigned* a,
                                         unsigned b0, unsigned b1) {
    asm volatile("mma.sync.aligned.m16n8k16.row.col.f32.f16.f16.f32 "
                 "{%0,%1,%2,%3}, {%4,%5,%6,%7}, {%8,%9}, {%0,%1,%2,%3};"
                 : "+f"(c[0]), "+f"(c[1]), "+f"(c[2]), "+f"(c[3])
                 : "r"(a[0]), "r"(a[1]), "r"(a[2]), "r"(a[3]), "r"(b0), "r"(b1));
}
__device__ __forceinline__ void cpa16(unsigned dst, const void* src) {
    asm volatile("cp.async.cg.shared.global [%0], [%1], 16;"
                 :: "r"(dst), "l"(src) : "memory");
}

// ---------------------------------------------------------------------------
// prep: hi/lo transposed codebook, wn, zero scratch
// ---------------------------------------------------------------------------
__global__ void prep_kernel(const float* __restrict__ weight) {
    int i = blockIdx.x * blockDim.x + threadIdx.x;   // 262144
    float w = weight[i];
    int code = i >> 6, c = i & 63;
    __half hi = __float2half_rn(w);
    __half lo = __float2half_rn(w - __half2float(hi));
    g_wth[(size_t)c * NUM_E + code] = hi;
    g_wtl[(size_t)c * NUM_E + code] = lo;
    g_dw[i] = 0.0f;
    if (i < NUM_E) {
        const float4* wrow = reinterpret_cast<const float4*>(weight + (size_t)i * CDIM);
        float s = 0.0f;
#pragma unroll
        for (int j = 0; j < CDIM / 4; ++j) {
            float4 v = wrow[j];
            s += v.x * v.x + v.y * v.y + v.z * v.z + v.w * v.w;
        }
        g_wn[i] = s;
        g_counts[i] = 0.0f;
    }
    if (i == 0) { g_loss = 0.0f; g_n = 0.0f; g_namb = 0; }
}

// ---------------------------------------------------------------------------
// argmin kernel: split-fp16 HMMA GEMM + streaming best/best2/argmin
// ---------------------------------------------------------------------------
__global__ void __launch_bounds__(THREADS, 1)
argmin_kernel(const float* __restrict__ inputs)
{
    extern __shared__ char smem[];
    const unsigned sb = smem_u32(smem);
    const int tid  = threadIdx.x;
    const int lane = tid & 31;
    const int wid  = tid >> 5;
    const int wm   = wid >> 1;
    const int wnh  = wid & 1;

    const int n0  = blockIdx.x * BM;
    const int bB  = n0 >> 12;
    const int hw0 = n0 & 4095;

    // ---- load X, split fp32 -> (hi, lo) fp16, swizzled ------------------
    const float* xb = inputs + (size_t)bB * (CDIM * 4096) + hw0;
#pragma unroll
    for (int it = 0; it < 4; ++it) {
        int idx = it * 256 + tid;
        int c = (idx & 31) * 2;
        int r = (idx >> 5) * 4;
        float4 f0 = *reinterpret_cast<const float4*>(xb + (size_t)c * 4096 + r);
        float4 f1 = *reinterpret_cast<const float4*>(xb + (size_t)(c + 1) * 4096 + r);
        const float* p0 = &f0.x; const float* p1 = &f1.x;
#pragma unroll
        for (int q = 0; q < 4; ++q) {
            int row = r + q;
            float a = p0[q], b = p1[q];
            __half ah = __float2half_rn(a), bh = __float2half_rn(b);
            __half al = __float2half_rn(a - __half2float(ah));
            __half bl = __float2half_rn(b - __half2float(bh));
            unsigned off = row * 128 + (((c >> 3) ^ (row & 7)) * 16) + (c & 7) * 2;
            *reinterpret_cast<__half2*>(smem + SM_XH + off) = __halves2half2(ah, bh);
            *reinterpret_cast<__half2*>(smem + SM_XL + off) = __halves2half2(al, bl);
        }
    }
    __syncthreads();

    // ---- A fragments hi + lo --------------------------------------------
    unsigned afh[2][4][4], afl[2][4][4];
#pragma unroll
    for (int i = 0; i < 2; ++i)
#pragma unroll
        for (int k = 0; k < 4; ++k) {
            int row = wm * 32 + i * 16 + (lane & 15);
            int ch  = (k * 2 + (lane >> 4)) ^ (row & 7);
            ldsm4(afh[i][k], sb + SM_XH + row * 128 + ch * 16);
            ldsm4(afl[i][k], sb + SM_XL + row * 128 + ch * 16);
        }

    unsigned boff[4][4];
#pragma unroll
    for (int k = 0; k < 4; ++k)
#pragma unroll
        for (int jj = 0; jj < 4; ++jj) {
            int row = k * 16 + (lane & 15);
            int ch  = (wnh * 8 + jj * 2 + (lane >> 4)) ^ (row & 7);
            boff[k][jj] = row * 256 + ch * 16;
        }

    float best[4], best2[4]; int bk[4];
#pragma unroll
    for (int s = 0; s < 4; ++s) { best[s] = 3.4e38f; best2[s] = 3.4e38f; bk[s] = 0; }

    const int wnidx = (wnh * 64 + 2 * (lane & 3)) * 4;

    // ---- prologue: stage tile 0 ------------------------------------------
    {
#pragma unroll
        for (int j = 0; j < 4; ++j) {
            int idx = j * 256 + tid;
            int row = idx >> 4, c = idx & 15;
            unsigned dsw = row * 256 + ((c ^ (row & 7)) * 16);
            cpa16(sb + SM_WBUF(0) + dsw, g_wth + (size_t)row * NUM_E + c * 8);
            cpa16(sb + SM_WLO(0)  + dsw, g_wtl + (size_t)row * NUM_E + c * 8);
        }
        if (tid < 32) cpa16(sb + SM_WN(0) + tid * 16, g_wn + tid * 4);
        asm volatile("cp.async.commit_group;" ::: "memory");
    }

    for (int t = 0; t < NTILES; ++t) {
        if (t + 1 < NTILES) {
            int kt = (t + 1) * BN, b = (t + 1) & 1;
#pragma unroll
            for (int j = 0; j < 4; ++j) {
                int idx = j * 256 + tid;
                int row = idx >> 4, c = idx & 15;
                unsigned dsw = row * 256 + ((c ^ (row & 7)) * 16);
                cpa16(sb + SM_WBUF(b) + dsw, g_wth + (size_t)row * NUM_E + kt + c * 8);
                cpa16(sb + SM_WLO(b)  + dsw, g_wtl + (size_t)row * NUM_E + kt + c * 8);
            }
            if (tid < 32) cpa16(sb + SM_WN(b) + tid * 16, g_wn + kt + tid * 4);
            asm volatile("cp.async.commit_group;" ::: "memory");
            asm volatile("cp.async.wait_group 1;" ::: "memory");
        } else {
            asm volatile("cp.async.wait_group 0;" ::: "memory");
        }
        __syncthreads();

        const unsigned whib = sb + SM_WBUF(t & 1);
        const unsigned wlob = sb + SM_WLO(t & 1);
        float acc[2][8][4];
#pragma unroll
        for (int i = 0; i < 2; ++i)
#pragma unroll
            for (int j = 0; j < 8; ++j)
#pragma unroll
                for (int e = 0; e < 4; ++e) acc[i][j][e] = 0.0f;

#pragma unroll
        for (int k = 0; k < 4; ++k) {
            unsigned bh[4][4], bl[4][4];
#pragma unroll
            for (int jj = 0; jj < 4; ++jj) {
                ldsm4t(bh[jj], whib + boff[k][jj]);
                ldsm4t(bl[jj], wlob + boff[k][jj]);
            }
#pragma unroll
            for (int i = 0; i < 2; ++i)
#pragma unroll
                for (int j = 0; j < 8; ++j) {
                    unsigned h0 = bh[j >> 1][(j & 1) * 2], h1 = bh[j >> 1][(j & 1) * 2 + 1];
                    unsigned l0 = bl[j >> 1][(j & 1) * 2], l1 = bl[j >> 1][(j & 1) * 2 + 1];
                    mma16816(acc[i][j], afh[i][k], h0, h1);   // hi*hi
                    mma16816(acc[i][j], afl[i][k], h0, h1);   // lo*hi
                    mma16816(acc[i][j], afh[i][k], l0, l1);   // hi*lo
                }
        }

        // ---- epilogue: scores + streaming 2-min --------------------------
        const int ktb = t * BN + wnh * 64 + 2 * (lane & 3);
        const char* wnst = smem + SM_WN(t & 1);
#pragma unroll
        for (int j = 0; j < 8; ++j) {
            float2 wn2 = *reinterpret_cast<const float2*>(wnst + wnidx + j * 32);
            int cb = ktb + j * 8;
#pragma unroll
            for (int i = 0; i < 2; ++i) {
#pragma unroll
                for (int hlf = 0; hlf < 2; ++hlf) {
                    int sl = i * 2 + hlf;
                    float s0 = fmaf(-2.0f, acc[i][j][hlf * 2 + 0], wn2.x);
                    float s1 = fmaf(-2.0f, acc[i][j][hlf * 2 + 1], wn2.y);
                    bool lt0 = s0 < best[sl];
                    float old0 = best[sl];
                    best[sl]  = lt0 ? s0 : old0;
                    best2[sl] = fminf(best2[sl], lt0 ? old0 : s0);
                    bk[sl]    = lt0 ? cb : bk[sl];
                    bool lt1 = s1 < best[sl];
                    float old1 = best[sl];
                    best[sl]  = lt1 ? s1 : old1;
                    best2[sl] = fminf(best2[sl], lt1 ? old1 : s1);
                    bk[sl]    = lt1 ? (cb + 1) : bk[sl];
                }
            }
        }
        __syncthreads();
    }

    // ---- cross-lane (quad) reduction --------------------------------------
#pragma unroll
    for (int off = 1; off <= 2; off <<= 1) {
#pragma unroll
        for (int s = 0; s < 4; ++s) {
            float ob  = __shfl_xor_sync(0xffffffffu, best[s], off);
            float ob2 = __shfl_xor_sync(0xffffffffu, best2[s], off);
            int   ok  = __shfl_xor_sync(0xffffffffu, bk[s], off);
            float nb2 = fminf(fminf(best2[s], ob2), fmaxf(best[s], ob));
            bool take = (ob < best[s]) || (ob == best[s] && ok < bk[s]);
            best[s] = take ? ob : best[s];
            bk[s]   = take ? ok : bk[s];
            best2[s] = nb2;
        }
    }

    // ---- stage + merge n-halves -------------------------------------------
    float* mB  = reinterpret_cast<float*>(smem);
    float* mB2 = mB + 256;
    int*   mK  = reinterpret_cast<int*>(mB2 + 256);
    __syncthreads();
    if ((lane & 3) == 0) {
#pragma unroll
        for (int s = 0; s < 4; ++s) {
            int row = wm * 32 + (s >> 1) * 16 + (lane >> 2) + (s & 1) * 8;
            mB [wnh * 128 + row] = best[s];
            mB2[wnh * 128 + row] = best2[s];
            mK [wnh * 128 + row] = bk[s];
        }
    }
    __syncthreads();
    if (tid < 128) {
        float b0 = mB[tid],  b1 = mB[128 + tid];
        float c0 = mB2[tid], c1 = mB2[128 + tid];
        int   k0 = mK[tid],  k1 = mK[128 + tid];
        float nb2 = fminf(fminf(c0, c1), fmaxf(b0, b1));
        float nb; int nk;
        if (b1 < b0 || (b1 == b0 && k1 < k0)) { nb = b1; nk = k1; }
        else                                   { nb = b0; nk = k0; }
        g_bestk[n0 + tid] = nk;
        bool amb = (nb2 - nb) < MARGIN;
        unsigned m = __ballot_sync(0xffffffffu, amb);
        int basep = 0;
        if (lane == 0 && m) basep = atomicAdd(&g_namb, __popc(m));
        basep = __shfl_sync(0xffffffffu, basep, 0);
        if (amb) g_amb[basep + __popc(m & ((1u << lane) - 1u))] = n0 + tid;
    }
}

// ---------------------------------------------------------------------------
// fixup: exact fp32 rescan for ambiguous vectors (expected: ~tens of rows)
// ---------------------------------------------------------------------------
__global__ void fixup_kernel(const float* __restrict__ inputs,
                             const float* __restrict__ weight)
{
    __shared__ float xs[CDIM];
    __shared__ float rs[8];
    __shared__ int   rk[8];
    const int tid = threadIdx.x;   // 256
    const int namb = g_namb;

    for (int li = blockIdx.x; li < namb; li += gridDim.x) {
        int v  = g_amb[li];
        int bB = v >> 12, hw = v & 4095;
        if (tid < CDIM)
            xs[tid] = inputs[(size_t)bB * (CDIM * 4096) + (size_t)tid * 4096 + hw];
        __syncthreads();

        float best = 3.4e38f; int bestk = 0;
        for (int k = tid; k < NUM_E; k += 256) {
            const float4* wr = reinterpret_cast<const float4*>(weight + (size_t)k * CDIM);
            float dot = 0.0f;
#pragma unroll
            for (int j = 0; j < 16; ++j) {
                float4 w4 = wr[j];
                dot = fmaf(xs[4 * j + 0], w4.x, dot);
                dot = fmaf(xs[4 * j + 1], w4.y, dot);
                dot = fmaf(xs[4 * j + 2], w4.z, dot);
                dot = fmaf(xs[4 * j + 3], w4.w, dot);
            }
            float s = fmaf(-2.0f, dot, g_wn[k]);
            if (s < best) { best = s; bestk = k; }
        }
#pragma unroll
        for (int o = 16; o > 0; o >>= 1) {
            float ob = __shfl_xor_sync(0xffffffffu, best, o);
            int   ok = __shfl_xor_sync(0xffffffffu, bestk, o);
            if (ob < best || (ob == best && ok < bestk)) { best = ob; bestk = ok; }
        }
        if ((tid & 31) == 0) { rs[tid >> 5] = best; rk[tid >> 5] = bestk; }
        __syncthreads();
        if (tid == 0) {
            float fb = rs[0]; int fk = rk[0];
#pragma unroll
            for (int w = 1; w < 8; ++w)
                if (rs[w] < fb || (rs[w] == fb && rk[w] < fk)) { fb = rs[w]; fk = rk[w]; }
            g_bestk[v] = fk;
        }
        __syncthreads();
    }
}

// ---------------------------------------------------------------------------
// scatter: idx out, counts, quantized gather (f4), loss, dw scatter
// ---------------------------------------------------------------------------
__global__ void scatter_kernel(const float* __restrict__ inputs,
                               const float* __restrict__ weight,
                               float* __restrict__ out)
{
    __shared__ int   idx_s[BM];
    __shared__ float red[8];
    const int tid = threadIdx.x;   // 256
    const int n0  = blockIdx.x * BM;
    const int bB  = n0 >> 12;
    const int hw0 = n0 & 4095;

    if (tid < BM) {
        int k = g_bestk[n0 + tid];
        idx_s[tid] = k;
        out[OFF_IDX + n0 + tid] = (float)k;
        atomicAdd(&g_counts[k], 1.0f);
    }
    __syncthreads();

    const float* xb = inputs + (size_t)bB * (CDIM * 4096) + hw0;
    float* outq     = out + OFF_Q + (size_t)bB * (CDIM * 4096) + hw0;
    float lsum = 0.0f;
    // 2048 units: (c, r4) — vectorized along rows
    for (int u = tid; u < CDIM * (BM / 4); u += 256) {
        int c  = u >> 5;           // 0..63
        int r4 = (u & 31) * 4;     // 0..124
        float4 x4 = *reinterpret_cast<const float4*>(xb + (size_t)c * 4096 + r4);
        float q0 = weight[(size_t)idx_s[r4 + 0] * CDIM + c];
        float q1 = weight[(size_t)idx_s[r4 + 1] * CDIM + c];
        float q2 = weight[(size_t)idx_s[r4 + 2] * CDIM + c];
        float q3 = weight[(size_t)idx_s[r4 + 3] * CDIM + c];
        *reinterpret_cast<float4*>(outq + (size_t)c * 4096 + r4) =
            make_float4(q0, q1, q2, q3);
        float d0 = x4.x - q0, d1 = x4.y - q1, d2 = x4.z - q2, d3 = x4.w - q3;
        lsum += d0 * d0 + d1 * d1 + d2 * d2 + d3 * d3;
        atomicAdd(&g_dw[idx_s[r4 + 0] * CDIM + c], x4.x);
        atomicAdd(&g_dw[idx_s[r4 + 1] * CDIM + c], x4.y);
        atomicAdd(&g_dw[idx_s[r4 + 2] * CDIM + c], x4.z);
        atomicAdd(&g_dw[idx_s[r4 + 3] * CDIM + c], x4.w);
    }
#pragma unroll
    for (int o = 16; o > 0; o >>= 1)
        lsum += __shfl_xor_sync(0xffffffffu, lsum, o);
    if ((tid & 31) == 0) red[tid >> 5] = lsum;
    __syncthreads();
    if (tid == 0) {
        float s = 0.0f;
#pragma unroll
        for (int w = 0; w < 8; ++w) s += red[w];
        atomicAdd(&g_loss, s);
    }
}

// ---------------------------------------------------------------------------
__global__ void finalize1_kernel(const float* __restrict__ ema_cs,
                                 float* __restrict__ out) {
    int k = blockIdx.x * blockDim.x + threadIdx.x;
    float ncs = 0.99f * ema_cs[k] + 0.01f * g_counts[k];
    out[OFF_CS + k] = ncs;
    float s = ncs;
#pragma unroll
    for (int o = 16; o > 0; o >>= 1)
        s += __shfl_xor_sync(0xffffffffu, s, o);
    __shared__ float sh[8];
    if ((threadIdx.x & 31) == 0) sh[threadIdx.x >> 5] = s;
    __syncthreads();
    if (threadIdx.x == 0) {
        float t = 0.0f;
#pragma unroll
        for (int w = 0; w < 8; ++w) t += sh[w];
        atomicAdd(&g_n, t);
    }
}

__global__ void finalize2_kernel(const float* __restrict__ ema_w,
                                 float* __restrict__ out) {
    int i = blockIdx.x * blockDim.x + threadIdx.x;
    int k = i >> 6;
    float n   = g_n;
    float ncs = out[OFF_CS + k];
    float cs  = (ncs + 1e-5f) / (n + (float)NUM_E * 1e-5f) * n;
    float ne  = 0.99f * ema_w[i] + 0.01f * g_dw[i];
    out[OFF_EW + i] = ne;
    out[OFF_W + i]  = ne / cs;
    if (i == 0) out[OFF_LOSS] = 0.25f * g_loss / 4194304.0f;
}

// ---------------------------------------------------------------------------
extern "C" void kernel_launch(void* const* d_in, const int* in_sizes, int n_in,
                              void* d_out, int out_size) {
    const float* inputs = (const float*)d_in[0];
    const float* weight = (const float*)d_in[1];
    const float* ema_cs = (const float*)d_in[2];
    const float* ema_w  = (const float*)d_in[3];
    float* out = (float*)d_out;

    cudaFuncSetAttribute(argmin_kernel,
                         cudaFuncAttributeMaxDynamicSharedMemorySize, SMEM_TOTAL);

    prep_kernel<<<(NUM_E * CDIM) / 256, 256>>>(weight);
    argmin_kernel<<<NVEC / BM, THREADS, SMEM_TOTAL>>>(inputs);
    fixup_kernel<<<512, 256>>>(inputs, weight);
    scatter_kernel<<<NVEC / BM, 256>>>(inputs, weight, out);
    finalize1_kernel<<<NUM_E / 256, 256>>>(ema_cs, out);
    finalize2_kernel<<<(NUM_E * CDIM) / 256, 256>>>(ema_w, out);
}